// round 7
// baseline (speedup 1.0000x reference)
#include <cuda_runtime.h>
#include <cstdint>

// out[i, 0:32] = weight[b[i], 0:32] (fp32), out[0, :] = 0.
// N = 1e6 rows -> output = 128 MB, just over the 126 MB L2.
//
// Bound by L2-overflow dirty writeback (~72 MB/launch @ ~3.3 TB/s DRAM
// write ceiling). Fix: address-partitioned residency with 256-bit
// stores (sm_103 requires .v8.b32 for L2 evict hints):
//   [0, RESID_OCT)  : st.global.L2::evict_last.v8.b32  -> stays in L2
//                     across graph replays, re-dirtied in place.
//   [RESID_OCT, ..) : st.global.L2::evict_first.v8.b32 -> streams to
//                     DRAM without displacing the resident set.

static constexpr int OCT_PER_ROW = 4;   // 32 floats / 8 per oct (32B)
static constexpr int TPB  = 256;
static constexpr int VPT  = 4;          // octs per thread
static constexpr int TILE = TPB * VPT;

// Resident region: 112 MB = 3.5M octs (leaves ~14 MB of L2 for the 4 MB
// index array, weight table, and slack).
static constexpr int RESID_OCT = 3584 * 1024;   // 3,670,016 octs = 112 MB

__device__ __forceinline__ void ldg256(const float* p, uint32_t r[8]) {
    asm volatile("ld.global.nc.v8.b32 {%0,%1,%2,%3,%4,%5,%6,%7}, [%8];"
                 : "=r"(r[0]), "=r"(r[1]), "=r"(r[2]), "=r"(r[3]),
                   "=r"(r[4]), "=r"(r[5]), "=r"(r[6]), "=r"(r[7])
                 : "l"(p));
}

__device__ __forceinline__ void st256_resident(float* p, const uint32_t r[8]) {
    asm volatile("st.global.L2::evict_last.v8.b32 [%0], {%1,%2,%3,%4,%5,%6,%7,%8};"
                 :: "l"(p),
                    "r"(r[0]), "r"(r[1]), "r"(r[2]), "r"(r[3]),
                    "r"(r[4]), "r"(r[5]), "r"(r[6]), "r"(r[7])
                 : "memory");
}

__device__ __forceinline__ void st256_stream(float* p, const uint32_t r[8]) {
    asm volatile("st.global.L2::evict_first.v8.b32 [%0], {%1,%2,%3,%4,%5,%6,%7,%8};"
                 :: "l"(p),
                    "r"(r[0]), "r"(r[1]), "r"(r[2]), "r"(r[3]),
                    "r"(r[4]), "r"(r[5]), "r"(r[6]), "r"(r[7])
                 : "memory");
}

__global__ __launch_bounds__(TPB) void gather_rows_v8_l2pin(
    const int* __restrict__ b,          // [N]
    const float* __restrict__ weight,   // [64, 32]
    float* __restrict__ out,            // [N*32]
    int n_oct)                          // N * 4
{
    int base = blockIdx.x * TILE + threadIdx.x;

    int  v[VPT];
    int  bi[VPT];
    bool ok[VPT];

    // Phase 1: indices (4 lanes broadcast per row; 4 MB array, L2-cached)
    #pragma unroll
    for (int k = 0; k < VPT; k++) {
        v[k]  = base + k * TPB;
        ok[k] = v[k] < n_oct;
        int row = v[k] >> 2;
        bi[k] = ok[k] ? __ldg(&b[row]) : 0;
    }

    // Phase 2: weight octs (8 KB table, L1-resident), 256-bit loads
    uint32_t val[VPT][8];
    #pragma unroll
    for (int k = 0; k < VPT; k++) {
        ldg256(weight + bi[k] * 32 + (v[k] & 3) * 8, val[k]);
        if ((v[k] >> 2) == 0) {
            #pragma unroll
            for (int j = 0; j < 8; j++) val[k][j] = 0u;
        }
    }

    // Phase 3: partitioned-policy 256-bit stores (warp-uniform branch:
    // v is contiguous across lanes, so the predicate splits at a warp
    // boundary except for one warp per kernel).
    #pragma unroll
    for (int k = 0; k < VPT; k++) {
        if (ok[k]) {
            float* p = out + (size_t)v[k] * 8;
            if (v[k] < RESID_OCT) st256_resident(p, val[k]);
            else                  st256_stream(p, val[k]);
        }
    }
}

extern "C" void kernel_launch(void* const* d_in, const int* in_sizes, int n_in,
                              void* d_out, int out_size) {
    const int*   b      = (const int*)d_in[0];
    const float* weight = (const float*)d_in[1];
    float*       out    = (float*)d_out;

    int n     = in_sizes[0];            // N rows
    int n_oct = n * OCT_PER_ROW;        // 4M octs

    int blocks = (n_oct + TILE - 1) / TILE;
    gather_rows_v8_l2pin<<<blocks, TPB>>>(b, weight, out, n_oct);
}

// round 8
// speedup vs baseline: 1.1401x; 1.1401x over previous
#include <cuda_runtime.h>
#include <cstdint>

// out[i, 0:32] = weight[b[i], 0:32]  (fp32), out[0, :] = 0.
// N = 1e6 rows, 8 float4 per row, 8M float4 total (128 MB).
//
// Empirical model (R2-R7): single-launch time is pinned at ~22us by the
// L2 store-path ceiling (~5.9 TB/s for a 128MB write stream) and is
// insensitive to DRAM traffic, vector width, and occupancy. In graph
// replay the winner is determined by INTER-launch L2 state: streaming
// (evict-first) stores keep L2 clean so the next replay's store misses
// don't stall on dirty evictions (bench delta ~2.4us). So: float4 +
// __stcs + VPT=4 + high occupancy, with the row-0 zeroing hoisted out
// of the hot path (only block 0 pays for it).

static constexpr int Y_DIM = 32;
static constexpr int VEC_PER_ROW = Y_DIM / 4;   // 8
static constexpr int TPB = 256;
static constexpr int VPT = 4;                    // float4 per thread
static constexpr int TILE = TPB * VPT;           // 1024 vec4 per block

__global__ __launch_bounds__(TPB) void gather_rows_stream(
    const int* __restrict__ b,          // [N]
    const float* __restrict__ weight,   // [64, 32]
    float4* __restrict__ out,           // [N*8] float4
    int n_vec)
{
    const float4* __restrict__ w4 = reinterpret_cast<const float4*>(weight);

    int base = blockIdx.x * TILE + threadIdx.x;

    if (blockIdx.x != 0) {
        // Hot path: no bounds check needed except in the last block;
        // keep it anyway (cheap, predicated) but skip the row-0 test.
        int  v[VPT];
        int  bi[VPT];
        bool ok[VPT];
        #pragma unroll
        for (int k = 0; k < VPT; k++) {
            v[k]  = base + k * TPB;
            ok[k] = v[k] < n_vec;
            bi[k] = ok[k] ? __ldg(&b[v[k] >> 3]) : 0;
        }
        float4 val[VPT];
        #pragma unroll
        for (int k = 0; k < VPT; k++)
            val[k] = __ldg(&w4[bi[k] * VEC_PER_ROW + (v[k] & 7)]);
        #pragma unroll
        for (int k = 0; k < VPT; k++)
            if (ok[k]) __stcs(&out[v[k]], val[k]);
    } else {
        // Block 0: identical flow plus the out[0,:] = 0 override.
        int  v[VPT];
        int  bi[VPT];
        #pragma unroll
        for (int k = 0; k < VPT; k++) {
            v[k]  = base + k * TPB;
            bi[k] = __ldg(&b[v[k] >> 3]);
        }
        float4 val[VPT];
        #pragma unroll
        for (int k = 0; k < VPT; k++) {
            val[k] = __ldg(&w4[bi[k] * VEC_PER_ROW + (v[k] & 7)]);
            if (v[k] < VEC_PER_ROW) val[k] = make_float4(0.f, 0.f, 0.f, 0.f);
        }
        #pragma unroll
        for (int k = 0; k < VPT; k++)
            __stcs(&out[v[k]], val[k]);
    }
}

extern "C" void kernel_launch(void* const* d_in, const int* in_sizes, int n_in,
                              void* d_out, int out_size) {
    const int*   b      = (const int*)d_in[0];
    const float* weight = (const float*)d_in[1];
    float4*      out    = (float4*)d_out;

    int n     = in_sizes[0];          // N rows
    int n_vec = n * VEC_PER_ROW;      // 8M float4

    int blocks = (n_vec + TILE - 1) / TILE;
    gather_rows_stream<<<blocks, TPB>>>(b, weight, out, n_vec);
}